// round 15
// baseline (speedup 1.0000x reference)
#include <cuda_runtime.h>
#include <cuda_fp16.h>
#include <math.h>
#include <stdint.h>

#define S_LEN 1024
#define BATCH 8
#define BS_TOT 8192          // B*S
#define INNER 288
#define DIMX 192
#define NHQ 72
#define NHM 4
#define DHM 72

// ---------------- scratch (static __device__, no allocations) ----------------
__device__ float  g_y [BS_TOT * 2 * INNER];  // proj_up output [8192,576]: x_m | z
__device__ float  g_xa[BS_TOT * INNER];      // silu(conv(x_m))
__device__ __align__(256) __half g_q [BS_TOT * INNER];  // fp16 (RNE)
__device__ __align__(256) __half g_k [BS_TOT * INNER];  // fp16 (RNE)
__device__ __align__(256) __half g_v [BS_TOT * INNER];  // fp16 (RNE)
__device__ float  g_ig[32 * S_LEN];          // [b*4+n][s]
__device__ float  g_fg[32 * S_LEN];
__device__ float  g_m [32 * S_LEN];          // exp(ig - lfc)  (pre-exponentiated)
__device__ float  g_Mx[32 * S_LEN];          // prefix max of m
__device__ float  g_d0[32 * S_LEN];          // exp(-lfc - M)
__device__ __align__(256) __half g_hs[BS_TOT * INNER];  // h_state (fp16)

// ---------------- helpers ----------------
__device__ __forceinline__ void mma_f16(float c[4], uint32_t a0, uint32_t a1,
                                        uint32_t a2, uint32_t a3,
                                        uint32_t b0, uint32_t b1) {
    asm volatile(
        "mma.sync.aligned.m16n8k16.row.col.f32.f16.f16.f32 "
        "{%0,%1,%2,%3}, {%4,%5,%6,%7}, {%8,%9}, {%0,%1,%2,%3};"
        : "+f"(c[0]), "+f"(c[1]), "+f"(c[2]), "+f"(c[3])
        : "r"(a0), "r"(a1), "r"(a2), "r"(a3), "r"(b0), "r"(b1));
}

__device__ __forceinline__ void mma_f16_k8(float c[4], uint32_t a0, uint32_t a1,
                                           uint32_t b0) {
    asm volatile(
        "mma.sync.aligned.m16n8k8.row.col.f32.f16.f16.f32 "
        "{%0,%1,%2,%3}, {%4,%5}, {%6}, {%0,%1,%2,%3};"
        : "+f"(c[0]), "+f"(c[1]), "+f"(c[2]), "+f"(c[3])
        : "r"(a0), "r"(a1), "r"(b0));
}

__device__ __forceinline__ void ldmx4(uint32_t& r0, uint32_t& r1, uint32_t& r2,
                                      uint32_t& r3, uint32_t addr) {
    asm volatile("ldmatrix.sync.aligned.m8n8.x4.shared.b16 {%0,%1,%2,%3}, [%4];"
                 : "=r"(r0), "=r"(r1), "=r"(r2), "=r"(r3) : "r"(addr));
}

__device__ __forceinline__ void ldmx4t(uint32_t& r0, uint32_t& r1, uint32_t& r2,
                                       uint32_t& r3, uint32_t addr) {
    asm volatile("ldmatrix.sync.aligned.m8n8.x4.trans.shared.b16 {%0,%1,%2,%3}, [%4];"
                 : "=r"(r0), "=r"(r1), "=r"(r2), "=r"(r3) : "r"(addr));
}

__device__ __forceinline__ uint32_t h2u(float a, float b) {
    __half2 h = __floats2half2_rn(a, b);
    return *reinterpret_cast<uint32_t*>(&h);
}

__device__ __forceinline__ void cp_async16(uint32_t dst, const void* src) {
    asm volatile("cp.async.cg.shared.global [%0], [%1], 16;" :: "r"(dst), "l"(src));
}
#define CP_COMMIT() asm volatile("cp.async.commit_group;" ::: "memory")
#define CP_WAIT0()  asm volatile("cp.async.wait_group 0;" ::: "memory")

// ---------------- fp16 GEMM (A fp32): C[M,N] = A[M,K] @ B[N,K]^T ----------------
template<int BM>
__global__ void __launch_bounds__(256) gemm_f16(
        const float* __restrict__ A, const float* __restrict__ Bm,
        float* __restrict__ C, int M, int N, int K) {
    constexpr int MF = BM / 32;
    constexpr int NCA = BM / 64;      // A 8-float chunks per thread
    __shared__ __half As[2][BM][40];
    __shared__ __half Bs[2][64][40];
    int r0 = blockIdx.y * BM, c0 = blockIdx.x * 64;
    int tid = threadIdx.x, lane = tid & 31, warp = tid >> 5;
    int wm = warp >> 2, wn = warp & 3;
    int mb = wm * (BM / 2), nb = wn * 16;
    int ln4 = lane >> 2, q4 = lane & 3;
    int lm = lane >> 3, lr = lane & 7;
    float acc[MF][2][4] = {};
    float4 pa[NCA][2], pb[2];

    int KT = K >> 5;

    #pragma unroll
    for (int u = 0; u < NCA; u++) {
        int c = tid + u * 256, row = c >> 2, cg = (c & 3) * 8;
        const float* src = &A[(size_t)(r0 + row) * K + cg];
        *(uint4*)&As[0][row][cg] = make_uint4(
            h2u(src[0], src[1]), h2u(src[2], src[3]),
            h2u(src[4], src[5]), h2u(src[6], src[7]));
    }
    {
        int row = tid >> 2, cg = (tid & 3) * 8;
        const float* src = &Bm[(size_t)(c0 + row) * K + cg];
        *(uint4*)&Bs[0][row][cg] = make_uint4(
            h2u(src[0], src[1]), h2u(src[2], src[3]),
            h2u(src[4], src[5]), h2u(src[6], src[7]));
    }
    __syncthreads();

    for (int kt = 0; kt < KT; kt++) {
        int cur = kt & 1, nxt = cur ^ 1;
        if (kt + 1 < KT) {
            int k0 = (kt + 1) * 32;
            #pragma unroll
            for (int u = 0; u < NCA; u++) {
                int c = tid + u * 256, row = c >> 2, cg = (c & 3) * 8;
                const float* src = &A[(size_t)(r0 + row) * K + k0 + cg];
                pa[u][0] = *(const float4*)src;
                pa[u][1] = *(const float4*)(src + 4);
            }
            {
                int row = tid >> 2, cg = (tid & 3) * 8;
                const float* src = &Bm[(size_t)(c0 + row) * K + k0 + cg];
                pb[0] = *(const float4*)src;
                pb[1] = *(const float4*)(src + 4);
            }
        }
        uint32_t asb = (uint32_t)__cvta_generic_to_shared(&As[cur][0][0]);
        uint32_t bsb = (uint32_t)__cvta_generic_to_shared(&Bs[cur][0][0]);
        #pragma unroll
        for (int ks = 0; ks < 32; ks += 16) {
            uint32_t kb0, kb1, kb2, kb3;
            {
                int nrow = nb + ((lm >> 1) << 3) + lr;
                int kcol = ks + ((lm & 1) << 3);
                ldmx4(kb0, kb1, kb2, kb3, bsb + (nrow * 40 + kcol) * 2);
            }
            #pragma unroll
            for (int mf = 0; mf < MF; mf++) {
                uint32_t a0, a1, a2, a3;
                int arow = mb + mf * 16 + ((lm & 1) << 3) + lr;
                int acol = ks + ((lm >> 1) << 3);
                ldmx4(a0, a1, a2, a3, asb + (arow * 40 + acol) * 2);
                mma_f16(acc[mf][0], a0, a1, a2, a3, kb0, kb1);
                mma_f16(acc[mf][1], a0, a1, a2, a3, kb2, kb3);
            }
        }
        if (kt + 1 < KT) {
            #pragma unroll
            for (int u = 0; u < NCA; u++) {
                int c = tid + u * 256, row = c >> 2, cg = (c & 3) * 8;
                *(uint4*)&As[nxt][row][cg] = make_uint4(
                    h2u(pa[u][0].x, pa[u][0].y), h2u(pa[u][0].z, pa[u][0].w),
                    h2u(pa[u][1].x, pa[u][1].y), h2u(pa[u][1].z, pa[u][1].w));
            }
            {
                int row = tid >> 2, cg = (tid & 3) * 8;
                *(uint4*)&Bs[nxt][row][cg] = make_uint4(
                    h2u(pb[0].x, pb[0].y), h2u(pb[0].z, pb[0].w),
                    h2u(pb[1].x, pb[1].y), h2u(pb[1].z, pb[1].w));
            }
            __syncthreads();
        }
    }

    #pragma unroll
    for (int mf = 0; mf < MF; mf++)
        #pragma unroll
        for (int nf = 0; nf < 2; nf++) {
            int row = r0 + mb + mf * 16 + ln4;
            int col = c0 + nb + nf * 8 + 2 * q4;
            C[(size_t)row * N + col]       = acc[mf][nf][0];
            C[(size_t)row * N + col + 1]   = acc[mf][nf][1];
            C[(size_t)(row + 8) * N + col]     = acc[mf][nf][2];
            C[(size_t)(row + 8) * N + col + 1] = acc[mf][nf][3];
        }
}

// ---------------- fp16 GEMM (A already fp16): BM=64 ----------------
__global__ void __launch_bounds__(256) gemm_f16h(
        const __half* __restrict__ A, const float* __restrict__ Bm,
        float* __restrict__ C, int M, int N, int K) {
    constexpr int BM = 64, MF = 2;
    __shared__ __half As[2][BM][40];
    __shared__ __half Bs[2][64][40];
    int r0 = blockIdx.y * BM, c0 = blockIdx.x * 64;
    int tid = threadIdx.x, lane = tid & 31, warp = tid >> 5;
    int wm = warp >> 2, wn = warp & 3;
    int mb = wm * 32, nb = wn * 16;
    int ln4 = lane >> 2, q4 = lane & 3;
    int lm = lane >> 3, lr = lane & 7;
    float acc[MF][2][4] = {};
    uint4 pa;
    float4 pb[2];

    int KT = K >> 5;
    int arow = tid >> 2, acg = (tid & 3) * 8;
    int brow = tid >> 2, bcg = (tid & 3) * 8;

    *(uint4*)&As[0][arow][acg] = *(const uint4*)&A[(size_t)(r0 + arow) * K + acg];
    {
        const float* src = &Bm[(size_t)(c0 + brow) * K + bcg];
        *(uint4*)&Bs[0][brow][bcg] = make_uint4(
            h2u(src[0], src[1]), h2u(src[2], src[3]),
            h2u(src[4], src[5]), h2u(src[6], src[7]));
    }
    __syncthreads();

    for (int kt = 0; kt < KT; kt++) {
        int cur = kt & 1, nxt = cur ^ 1;
        if (kt + 1 < KT) {
            int k0 = (kt + 1) * 32;
            pa = *(const uint4*)&A[(size_t)(r0 + arow) * K + k0 + acg];
            const float* src = &Bm[(size_t)(c0 + brow) * K + k0 + bcg];
            pb[0] = *(const float4*)src;
            pb[1] = *(const float4*)(src + 4);
        }
        uint32_t asb = (uint32_t)__cvta_generic_to_shared(&As[cur][0][0]);
        uint32_t bsb = (uint32_t)__cvta_generic_to_shared(&Bs[cur][0][0]);
        #pragma unroll
        for (int ks = 0; ks < 32; ks += 16) {
            uint32_t kb0, kb1, kb2, kb3;
            {
                int nrow = nb + ((lm >> 1) << 3) + lr;
                int kcol = ks + ((lm & 1) << 3);
                ldmx4(kb0, kb1, kb2, kb3, bsb + (nrow * 40 + kcol) * 2);
            }
            #pragma unroll
            for (int mf = 0; mf < MF; mf++) {
                uint32_t a0, a1, a2, a3;
                int ar = mb + mf * 16 + ((lm & 1) << 3) + lr;
                int ac = ks + ((lm >> 1) << 3);
                ldmx4(a0, a1, a2, a3, asb + (ar * 40 + ac) * 2);
                mma_f16(acc[mf][0], a0, a1, a2, a3, kb0, kb1);
                mma_f16(acc[mf][1], a0, a1, a2, a3, kb2, kb3);
            }
        }
        if (kt + 1 < KT) {
            *(uint4*)&As[nxt][arow][acg] = pa;
            *(uint4*)&Bs[nxt][brow][bcg] = make_uint4(
                h2u(pb[0].x, pb[0].y), h2u(pb[0].z, pb[0].w),
                h2u(pb[1].x, pb[1].y), h2u(pb[1].z, pb[1].w));
            __syncthreads();
        }
    }

    #pragma unroll
    for (int mf = 0; mf < MF; mf++)
        #pragma unroll
        for (int nf = 0; nf < 2; nf++) {
            int row = r0 + mb + mf * 16 + ln4;
            int col = c0 + nb + nf * 8 + 2 * q4;
            C[(size_t)row * N + col]       = acc[mf][nf][0];
            C[(size_t)row * N + col + 1]   = acc[mf][nf][1];
            C[(size_t)(row + 8) * N + col]     = acc[mf][nf][2];
            C[(size_t)(row + 8) * N + col + 1] = acc[mf][nf][3];
        }
}

// ---------------- fused conv3x3+silu + qkv + gates (unchanged) ----------------
__global__ void __launch_bounds__(256) fused_mid_kernel(
        const float* __restrict__ cw,
        const float* __restrict__ qw, const float* __restrict__ kw,
        const float* __restrict__ vw,
        const float* __restrict__ igw, const float* __restrict__ igb,
        const float* __restrict__ fgw, const float* __restrict__ fgb) {
    extern __shared__ float4 smf4[];
    float4* sig4 = smf4;            // 864
    float4* sfg4 = sig4 + 864;      // 864

    int tid = threadIdx.x;
    for (int i = tid; i < 864; i += 256) { sig4[i] = ((const float4*)igw)[i]; sfg4[i] = ((const float4*)fgw)[i]; }
    __syncthreads();

    int warp = tid >> 5, lane = tid & 31;
    int bs = blockIdx.x * 8 + warp;
    int hw = bs & 1023, b = bs >> 10;
    int h = hw >> 5, w = hw & 31;

    float ai[4] = {0, 0, 0, 0}, af[4] = {0, 0, 0, 0};

    #pragma unroll
    for (int pass = 0; pass < 3; pass++) {
        int hd = pass * 32 + lane;
        if (pass == 2 && lane >= 8) break;
        int c = hd * 4;
        float4 acc = make_float4(0.f, 0.f, 0.f, 0.f);
        float4 xm = make_float4(0.f, 0.f, 0.f, 0.f);
        #pragma unroll
        for (int dh = -1; dh <= 1; dh++) {
            int hh = h + dh;
            if ((unsigned)hh >= 32u) continue;
            #pragma unroll
            for (int dw = -1; dw <= 1; dw++) {
                int ww = w + dw;
                if ((unsigned)ww >= 32u) continue;
                float4 xv = *(const float4*)&g_y[(size_t)(b * S_LEN + hh * 32 + ww) * (2 * INNER) + c];
                float4 wv = __ldg((const float4*)&cw[((dh + 1) * 3 + (dw + 1)) * INNER + c]);
                acc.x += xv.x * wv.x; acc.y += xv.y * wv.y;
                acc.z += xv.z * wv.z; acc.w += xv.w * wv.w;
                if (dh == 0 && dw == 0) xm = xv;
            }
        }
        float4 xa;
        xa.x = acc.x / (1.f + expf(-acc.x));
        xa.y = acc.y / (1.f + expf(-acc.y));
        xa.z = acc.z / (1.f + expf(-acc.z));
        xa.w = acc.w / (1.f + expf(-acc.w));
        *(float4*)&g_xa[(size_t)bs * INNER + c] = xa;

        float qo[4], ko[4], vo[4];
        #pragma unroll
        for (int o = 0; o < 4; o++) {
            float4 wq = __ldg((const float4*)&qw[hd * 16 + o * 4]);
            float4 wk = __ldg((const float4*)&kw[hd * 16 + o * 4]);
            float4 wv2 = __ldg((const float4*)&vw[hd * 16 + o * 4]);
            qo[o] = xa.x * wq.x + xa.y * wq.y + xa.z * wq.z + xa.w * wq.w;
            ko[o] = xa.x * wk.x + xa.y * wk.y + xa.z * wk.z + xa.w * wk.w;
            vo[o] = xm.x * wv2.x + xm.y * wv2.y + xm.z * wv2.z + xm.w * wv2.w;
        }
        uint2 qu = make_uint2(h2u(qo[0], qo[1]), h2u(qo[2], qo[3]));
        uint2 ku = make_uint2(h2u(ko[0], ko[1]), h2u(ko[2], ko[3]));
        uint2 vu = make_uint2(h2u(vo[0], vo[1]), h2u(vo[2], vo[3]));
        *(uint2*)&g_q[(size_t)bs * INNER + c] = qu;
        *(uint2*)&g_k[(size_t)bs * INNER + c] = ku;
        *(uint2*)&g_v[(size_t)bs * INNER + c] = vu;

        #pragma unroll
        for (int n = 0; n < 4; n++) {
            float4 wv4;
            wv4 = sig4[n * 216 + hd];
            ai[n] += qo[0] * wv4.x + qo[1] * wv4.y + qo[2] * wv4.z + qo[3] * wv4.w;
            wv4 = sig4[n * 216 + 72 + hd];
            ai[n] += ko[0] * wv4.x + ko[1] * wv4.y + ko[2] * wv4.z + ko[3] * wv4.w;
            wv4 = sig4[n * 216 + 144 + hd];
            ai[n] += vo[0] * wv4.x + vo[1] * wv4.y + vo[2] * wv4.z + vo[3] * wv4.w;
            wv4 = sfg4[n * 216 + hd];
            af[n] += qo[0] * wv4.x + qo[1] * wv4.y + qo[2] * wv4.z + qo[3] * wv4.w;
            wv4 = sfg4[n * 216 + 72 + hd];
            af[n] += ko[0] * wv4.x + ko[1] * wv4.y + ko[2] * wv4.z + ko[3] * wv4.w;
            wv4 = sfg4[n * 216 + 144 + hd];
            af[n] += vo[0] * wv4.x + vo[1] * wv4.y + vo[2] * wv4.z + vo[3] * wv4.w;
        }
    }
    #pragma unroll
    for (int off = 16; off; off >>= 1) {
        #pragma unroll
        for (int n = 0; n < 4; n++) {
            ai[n] += __shfl_xor_sync(0xffffffffu, ai[n], off);
            af[n] += __shfl_xor_sync(0xffffffffu, af[n], off);
        }
    }
    if (lane == 0) {
        int b2 = bs >> 10, s = bs & 1023;
        #pragma unroll
        for (int n = 0; n < 4; n++) {
            g_ig[(size_t)(b2 * 4 + n) * S_LEN + s] = ai[n] + igb[n];
            g_fg[(size_t)(b2 * 4 + n) * S_LEN + s] = af[n] + fgb[n];
        }
    }
}

// ---------------- scan: now stores exp(m) in g_m ----------------
__global__ void scan_kernel() {
    __shared__ float wbuf[32];
    int t = threadIdx.x, lane = t & 31, wid = t >> 5;
    int base = blockIdx.x * S_LEN;
    float fgv = g_fg[base + t];
    float lf = fminf(fgv, 0.f) - log1pf(expf(-fabsf(fgv)));
    float v = lf;
    #pragma unroll
    for (int o = 1; o < 32; o <<= 1) {
        float u = __shfl_up_sync(0xffffffffu, v, o);
        if (lane >= o) v += u;
    }
    if (lane == 31) wbuf[wid] = v;
    __syncthreads();
    if (wid == 0) {
        float s = wbuf[lane];
        #pragma unroll
        for (int o = 1; o < 32; o <<= 1) {
            float u = __shfl_up_sync(0xffffffffu, s, o);
            if (lane >= o) s += u;
        }
        wbuf[lane] = s;
    }
    __syncthreads();
    float lfc = v + (wid ? wbuf[wid - 1] : 0.f);
    float m = g_ig[base + t] - lfc;
    __syncthreads();
    float mx = m;
    #pragma unroll
    for (int o = 1; o < 32; o <<= 1) {
        float u = __shfl_up_sync(0xffffffffu, mx, o);
        if (lane >= o) mx = fmaxf(mx, u);
    }
    if (lane == 31) wbuf[wid] = mx;
    __syncthreads();
    if (wid == 0) {
        float s = wbuf[lane];
        #pragma unroll
        for (int o = 1; o < 32; o <<= 1) {
            float u = __shfl_up_sync(0xffffffffu, s, o);
            if (lane >= o) s = fmaxf(s, u);
        }
        wbuf[lane] = s;
    }
    __syncthreads();
    float Mv = wid ? fmaxf(mx, wbuf[wid - 1]) : mx;
    g_m [base + t] = expf(m);            // pre-exponentiated
    g_Mx[base + t] = Mv;
    g_d0[base + t] = expf(-lfc - Mv);
}

// ---------------- mLSTM attention v9: balanced pairing + k8 tail + plain wms load ----------------
#define KVSLOT 2816   // u32 per slab: 64 rows * 44 u32 (88 halves)
__global__ void __launch_bounds__(256, 2) attn_kernel(const float* __restrict__ normw,
                                                      const float* __restrict__ skipw) {
    extern __shared__ uint32_t smu[];
    uint32_t* Ks = smu;                     // 2 slabs
    uint32_t* Vs = smu + 2 * KVSLOT;        // 2 slabs
    float* wms = (float*)(smu + 4 * KVSLOT);  // 2 x 64

    int bn = blockIdx.y;
    int b = bn >> 2, n = bn & 3;
    int tid = threadIdx.x, lane = tid & 31, warp = tid >> 5;
    int wm = warp & 3, wn = warp >> 2;      // 4 row-groups x 2 k-halves
    int ln4 = lane >> 2, q4 = lane & 3;
    int r0 = wm * 16;
    int cb0 = wn * 32;
    int rr = r0 + ln4;
    const float scale = 0.11785113019775793f;  // 1/sqrt(72)
    const unsigned FULL = 0xffffffffu;

    uint32_t smbase = (uint32_t)__cvta_generic_to_shared(smu);

    // precompute staging indices (loop-invariant)
    int sOffG[5], sOffS[5];
    bool sIsV[5], sOK[5];
    #pragma unroll
    for (int u = 0; u < 5; u++) {
        int i = tid + u * 256;
        sOK[u]  = (i < 1152);
        sIsV[u] = (i >= 576);
        int j = sIsV[u] ? i - 576 : i;
        int r = j / 9, ch = j - r * 9;
        sOffG[u] = r * INNER + ch * 8;
        sOffS[u] = r * 44 + ch * 4;
    }

    int lm = lane >> 3, lr = lane & 7;

    #pragma unroll 1
    for (int sub = 0; sub < 2; sub++) {
        int R = sub == 0 ? (gridDim.x * 2 - 1 - blockIdx.x) : blockIdx.x;
        int S0 = R * 64;

        if (sub) __syncthreads();   // prior sub's smem reads complete

        // pads (halves 72..87; V col72 = 1.0)
        for (int i = tid; i < 2048; i += 256) {
            int slab = i >> 9, rem = i & 511;
            int r = rem >> 3, cc = 36 + (rem & 7);
            uint32_t val = (slab >= 2 && cc == 36) ? 0x00003C00u : 0u;
            smu[slab * KVSLOT + r * 44 + cc] = val;
        }
        float w0 = expf(-g_Mx[(size_t)bn * S_LEN + S0 + rr]) * scale;
        float w1 = expf(-g_Mx[(size_t)bn * S_LEN + S0 + rr + 8]) * scale;
        float d00 = g_d0[(size_t)bn * S_LEN + S0 + rr];
        float d01 = g_d0[(size_t)bn * S_LEN + S0 + rr + 8];
        if (tid < 64) wms[tid] = g_m[(size_t)bn * S_LEN + tid];  // tile 0 (pre-exp)

        const __half* kb = g_k + (size_t)(b * S_LEN) * INNER + n * 72;
        const __half* vb = g_v + (size_t)(b * S_LEN) * INNER + n * 72;

        #pragma unroll
        for (int u = 0; u < 5; u++) {
            if (!sOK[u]) continue;
            const __half* src = (sIsV[u] ? vb : kb) + sOffG[u];
            uint32_t* dst = (sIsV[u] ? Vs : Ks) + sOffS[u];
            cp_async16((uint32_t)__cvta_generic_to_shared(dst), src);
        }
        CP_COMMIT();

        uint32_t qf[5][4];
        {
            const __half* q0 = g_q + (size_t)(b * S_LEN + S0 + r0 + ln4) * INNER + n * 72;
            const __half* q1 = q0 + 8 * INNER;
            #pragma unroll
            for (int s = 0; s < 5; s++) {
                int c = s * 16 + 2 * q4;
                qf[s][0] = *(const uint32_t*)(q0 + c);
                qf[s][1] = *(const uint32_t*)(q1 + c);
                int c2 = c + 8;
                if (s < 4) {
                    qf[s][2] = *(const uint32_t*)(q0 + c2);
                    qf[s][3] = *(const uint32_t*)(q1 + c2);
                } else {
                    qf[s][2] = 0u; qf[s][3] = 0u;   // dead (k8 tail)
                }
            }
        }
        __syncthreads();

        float o[10][4] = {};

        for (int ct = 0; ct <= R; ct++) {
            CP_WAIT0();
            __syncthreads();
            int cur = ct & 1, nxt = cur ^ 1;
            if (ct < R) {
                kb += 64 * INNER;
                vb += 64 * INNER;
                uint32_t* Kd = Ks + nxt * KVSLOT;
                uint32_t* Vd = Vs + nxt * KVSLOT;
                #pragma unroll
                for (int u = 0; u < 5; u++) {
                    if (!sOK[u]) continue;
                    const __half* src = (sIsV[u] ? vb : kb) + sOffG[u];
                    uint32_t* dst = (sIsV[u] ? Vd : Kd) + sOffS[u];
                    cp_async16((uint32_t)__cvta_generic_to_shared(dst), src);
                }
                CP_COMMIT();
                if (tid < 64) wms[nxt * 64 + tid] = g_m[(size_t)bn * S_LEN + (ct + 1) * 64 + tid];
            }
            uint32_t kbase = smbase + (cur * KVSLOT) * 4;
            uint32_t vbase = smbase + ((2 + cur) * KVSLOT) * 4;
            const float* wmc = wms + cur * 64;

            float pc[4][4] = {};
            #pragma unroll
            for (int s = 0; s < 5; s++) {
                #pragma unroll
                for (int p = 0; p < 2; p++) {
                    int nrow = cb0 + p * 16 + ((lm >> 1) << 3) + lr;
                    int kcol = s * 16 + ((lm & 1) << 3);
                    uint32_t addr = kbase + nrow * 176 + kcol * 2;
                    uint32_t kb0, kb1, kb2, kb3;
                    ldmx4(kb0, kb1, kb2, kb3, addr);
                    if (s < 4) {
                        mma_f16(pc[2 * p],     qf[s][0], qf[s][1], qf[s][2], qf[s][3], kb0, kb1);
                        mma_f16(pc[2 * p + 1], qf[s][0], qf[s][1], qf[s][2], qf[s][3], kb2, kb3);
                    } else {
                        mma_f16_k8(pc[2 * p],     qf[s][0], qf[s][1], kb0);
                        mma_f16_k8(pc[2 * p + 1], qf[s][0], qf[s][1], kb2);
                    }
                }
            }

            bool diag = (ct == R);
            uint32_t pa[2][4];
            #pragma unroll
            for (int p = 0; p < 2; p++) {
                #pragma unroll
                for (int hh = 0; hh < 2; hh++) {
                    int nf = 2 * p + hh;
                    int c0 = cb0 + nf * 8 + 2 * q4;
                    float wc0 = wmc[c0], wc1 = wmc[c0 + 1];
                    float v00 = pc[nf][0] * w0 * wc0;
                    float v01 = pc[nf][1] * w0 * wc1;
                    float v10 = pc[nf][2] * w1 * wc0;
                    float v11 = pc[nf][3] * w1 * wc1;
                    if (diag) {
                        if (c0 > rr)         v00 = 0.f;
                        if (c0 + 1 > rr)     v01 = 0.f;
                        if (c0 > rr + 8)     v10 = 0.f;
                        if (c0 + 1 > rr + 8) v11 = 0.f;
                    }
                    pa[p][hh * 2 + 0] = h2u(v00, v01);
                    pa[p][hh * 2 + 1] = h2u(v10, v11);
                }
            }

            #pragma unroll
            for (int p = 0; p < 2; p++) {
                int kb2 = cb0 + p * 16;
                #pragma unroll
                for (int pf = 0; pf < 5; pf++) {
                    int vrow = kb2 + ((lm & 1) << 3) + lr;
                    int vcol = pf * 16 + ((lm >> 1) << 3);
                    uint32_t addr = vbase + vrow * 176 + vcol * 2;
                    uint32_t vb0, vb1, vb2, vb3;
                    ldmx4t(vb0, vb1, vb2, vb3, addr);
                    mma_f16(o[2 * pf],     pa[p][0], pa[p][1], pa[p][2], pa[p][3], vb0, vb1);
                    mma_f16(o[2 * pf + 1], pa[p][0], pa[p][1], pa[p][2], pa[p][3], vb2, vb3);
                }
            }
        }

        __syncthreads();
        float* OsB = (float*)Ks;
        if (wn == 1) {
            #pragma unroll
            for (int nf = 0; nf < 9; nf++) {
                int c = nf * 8 + 2 * q4;
                OsB[rr * 76 + c]           = o[nf][0];
                OsB[rr * 76 + c + 1]       = o[nf][1];
                OsB[(rr + 8) * 76 + c]     = o[nf][2];
                OsB[(rr + 8) * 76 + c + 1] = o[nf][3];
            }
            if (q4 == 0) {
                OsB[rr * 76 + 72]       = o[9][0];
                OsB[(rr + 8) * 76 + 72] = o[9][2];
            }
        }
        __syncthreads();
        float* Of = (float*)Vs;
        if (wn == 0) {
            float p0 = __shfl_sync(FULL, o[9][0], lane & 28);
            float p1 = __shfl_sync(FULL, o[9][2], lane & 28);
            float rs0 = p0 + OsB[rr * 76 + 72];
            float rs1 = p1 + OsB[(rr + 8) * 76 + 72];
            float inv0 = 1.f / (fmaxf(fabsf(rs0), d00) + 1e-6f);
            float inv1 = 1.f / (fmaxf(fabsf(rs1), d01) + 1e-6f);
            #pragma unroll
            for (int nf = 0; nf < 9; nf++) {
                int c = nf * 8 + 2 * q4;
                Of[rr * 76 + c]           = (o[nf][0] + OsB[rr * 76 + c])           * inv0;
                Of[rr * 76 + c + 1]       = (o[nf][1] + OsB[rr * 76 + c + 1])       * inv0;
                Of[(rr + 8) * 76 + c]     = (o[nf][2] + OsB[(rr + 8) * 76 + c])     * inv1;
                Of[(rr + 8) * 76 + c + 1] = (o[nf][3] + OsB[(rr + 8) * 76 + c + 1]) * inv1;
            }
        }
        __syncthreads();

        float nw0 = normw[n * 72 + lane];
        float sk0 = skipw[n * 72 + lane];
        float nw1 = normw[n * 72 + 32 + lane];
        float sk1 = skipw[n * 72 + 32 + lane];
        float nw2 = 0.f, sk2 = 0.f;
        if (lane < 8) { nw2 = normw[n * 72 + 64 + lane]; sk2 = skipw[n * 72 + 64 + lane]; }

        #pragma unroll
        for (int r8 = 0; r8 < 8; r8++) {
            int r = warp * 8 + r8;
            float h0 = Of[r * 76 + lane];
            float h1 = Of[r * 76 + 32 + lane];
            float h2 = (lane < 8) ? Of[r * 76 + 64 + lane] : 0.f;
            float psum = h0 + h1 + h2;
            #pragma unroll
            for (int off = 16; off; off >>= 1) psum += __shfl_xor_sync(FULL, psum, off);
            float mean = psum * (1.f / 72.f);
            float dv0 = h0 - mean, dv1 = h1 - mean, dv2 = h2 - mean;
            float pss = dv0 * dv0 + dv1 * dv1 + ((lane < 8) ? dv2 * dv2 : 0.f);
            #pragma unroll
            for (int off = 16; off; off >>= 1) pss += __shfl_xor_sync(FULL, pss, off);
            float rstd = rsqrtf(pss * (1.f / 72.f) + 1e-5f);

            size_t row  = (size_t)(b * S_LEN + S0 + r) * INNER;
            size_t zrow = (size_t)(b * S_LEN + S0 + r) * (2 * INNER) + INNER;
            {
                int c = n * 72 + lane;
                float z = g_y[zrow + c];
                float val = dv0 * rstd * nw0 + sk0 * g_xa[row + c];
                g_hs[row + c] = __float2half_rn(val * (z / (1.f + expf(-z))));
            }
            {
                int c = n * 72 + 32 + lane;
                float z = g_y[zrow + c];
                float val = dv1 * rstd * nw1 + sk1 * g_xa[row + c];
                g_hs[row + c] = __float2half_rn(val * (z / (1.f + expf(-z))));
            }
            if (lane < 8) {
                int c = n * 72 + 64 + lane;
                float z = g_y[zrow + c];
                float val = dv2 * rstd * nw2 + sk2 * g_xa[row + c];
                g_hs[row + c] = __float2half_rn(val * (z / (1.f + expf(-z))));
            }
        }
    }
}

// ---------------- launch ----------------
extern "C" void kernel_launch(void* const* d_in, const int* in_sizes, int n_in,
                              void* d_out, int out_size) {
    const float* x           = (const float*)d_in[0];
    const float* proj_up_w   = (const float*)d_in[1];
    const float* q_w         = (const float*)d_in[2];
    const float* k_w         = (const float*)d_in[3];
    const float* v_w         = (const float*)d_in[4];
    const float* conv_w      = (const float*)d_in[5];
    const float* ig_w        = (const float*)d_in[6];
    const float* ig_b        = (const float*)d_in[7];
    const float* fg_w        = (const float*)d_in[8];
    const float* fg_b        = (const float*)d_in[9];
    const float* norm_w      = (const float*)d_in[10];
    const float* skip        = (const float*)d_in[11];
    const float* proj_down_w = (const float*)d_in[12];
    float* out = (float*)d_out;

    float* py;
    __half* phs;
    cudaGetSymbolAddress((void**)&py,  g_y);
    cudaGetSymbolAddress((void**)&phs, g_hs);

    // 1) proj_up
    gemm_f16<128><<<dim3(576 / 64, BS_TOT / 128), 256>>>(x, proj_up_w, py, BS_TOT, 2 * INNER, DIMX);

    // 2) fused conv+silu+qkv+gates
    size_t smem_mid = (size_t)2 * 864 * 16;
    fused_mid_kernel<<<BS_TOT / 8, 256, smem_mid>>>(conv_w, q_w, k_w, v_w,
                                                    ig_w, ig_b, fg_w, fg_b);

    // 3) scan (stores exp(m))
    scan_kernel<<<32, S_LEN>>>();

    // 4) attention + LN + skip + silu(z): 8 balanced pairs x 32 bn
    size_t smem_attn = (size_t)(4 * KVSLOT + 128) * 4;
    cudaFuncSetAttribute(attn_kernel, cudaFuncAttributeMaxDynamicSharedMemorySize, (int)smem_attn);
    attn_kernel<<<dim3(8, 32), 256, smem_attn>>>(norm_w, skip);

    // 5) proj_down (A fp16)
    gemm_f16h<<<dim3(DIMX / 64, BS_TOT / 64), 256>>>(phs, proj_down_w, out, BS_TOT, DIMX, INNER);
}

// round 16
// speedup vs baseline: 1.0482x; 1.0482x over previous
#include <cuda_runtime.h>
#include <cuda_fp16.h>
#include <math.h>
#include <stdint.h>

#define S_LEN 1024
#define BATCH 8
#define BS_TOT 8192          // B*S
#define INNER 288
#define DIMX 192
#define NHQ 72
#define NHM 4
#define DHM 72

// ---------------- scratch (static __device__, no allocations) ----------------
__device__ float  g_y [BS_TOT * 2 * INNER];  // proj_up output [8192,576]: x_m | z
__device__ float  g_xa[BS_TOT * INNER];      // silu(conv(x_m))
__device__ __align__(256) __half g_q [BS_TOT * INNER];  // fp16 (RNE)
__device__ __align__(256) __half g_k [BS_TOT * INNER];  // fp16 (RNE)
__device__ __align__(256) __half g_v [BS_TOT * INNER];  // fp16 (RNE)
__device__ float  g_ig[32 * S_LEN];          // [b*4+n][s]
__device__ float  g_fg[32 * S_LEN];
__device__ float  g_m [32 * S_LEN];          // exp(ig - lfc)  (pre-exponentiated)
__device__ float  g_Mx[32 * S_LEN];          // prefix max of m
__device__ float  g_d0[32 * S_LEN];          // exp(-lfc - M)
__device__ __align__(256) __half g_hs[BS_TOT * INNER];  // h_state (fp16)
// pre-converted fp16 GEMM operands
__device__ __align__(256) __half g_xh  [BS_TOT * DIMX];   // x fp16
__device__ __align__(256) __half g_wuph[2 * INNER * DIMX];// W_up fp16
__device__ __align__(256) __half g_wdnh[DIMX * INNER];    // W_down fp16

#define XE (BS_TOT * DIMX)        // 1572864
#define UE (2 * INNER * DIMX)     // 110592
#define DE (DIMX * INNER)         // 55296

// ---------------- helpers ----------------
__device__ __forceinline__ void mma_f16(float c[4], uint32_t a0, uint32_t a1,
                                        uint32_t a2, uint32_t a3,
                                        uint32_t b0, uint32_t b1) {
    asm volatile(
        "mma.sync.aligned.m16n8k16.row.col.f32.f16.f16.f32 "
        "{%0,%1,%2,%3}, {%4,%5,%6,%7}, {%8,%9}, {%0,%1,%2,%3};"
        : "+f"(c[0]), "+f"(c[1]), "+f"(c[2]), "+f"(c[3])
        : "r"(a0), "r"(a1), "r"(a2), "r"(a3), "r"(b0), "r"(b1));
}

__device__ __forceinline__ void mma_f16_k8(float c[4], uint32_t a0, uint32_t a1,
                                           uint32_t b0) {
    asm volatile(
        "mma.sync.aligned.m16n8k8.row.col.f32.f16.f16.f32 "
        "{%0,%1,%2,%3}, {%4,%5}, {%6}, {%0,%1,%2,%3};"
        : "+f"(c[0]), "+f"(c[1]), "+f"(c[2]), "+f"(c[3])
        : "r"(a0), "r"(a1), "r"(b0));
}

__device__ __forceinline__ void ldmx4(uint32_t& r0, uint32_t& r1, uint32_t& r2,
                                      uint32_t& r3, uint32_t addr) {
    asm volatile("ldmatrix.sync.aligned.m8n8.x4.shared.b16 {%0,%1,%2,%3}, [%4];"
                 : "=r"(r0), "=r"(r1), "=r"(r2), "=r"(r3) : "r"(addr));
}

__device__ __forceinline__ void ldmx4t(uint32_t& r0, uint32_t& r1, uint32_t& r2,
                                       uint32_t& r3, uint32_t addr) {
    asm volatile("ldmatrix.sync.aligned.m8n8.x4.trans.shared.b16 {%0,%1,%2,%3}, [%4];"
                 : "=r"(r0), "=r"(r1), "=r"(r2), "=r"(r3) : "r"(addr));
}

__device__ __forceinline__ uint32_t h2u(float a, float b) {
    __half2 h = __floats2half2_rn(a, b);
    return *reinterpret_cast<uint32_t*>(&h);
}

__device__ __forceinline__ void cp_async16(uint32_t dst, const void* src) {
    asm volatile("cp.async.cg.shared.global [%0], [%1], 16;" :: "r"(dst), "l"(src));
}
#define CP_COMMIT() asm volatile("cp.async.commit_group;" ::: "memory")
#define CP_WAIT0()  asm volatile("cp.async.wait_group 0;" ::: "memory")

// ---------------- fp32 -> fp16 convert (x, W_up, W_down) ----------------
__global__ void __launch_bounds__(256) cvt_kernel(const float* __restrict__ x,
                                                  const float* __restrict__ wup,
                                                  const float* __restrict__ wdn) {
    int base = (blockIdx.x * 256 + threadIdx.x) * 8;
    const float* src;
    __half* dst;
    int off;
    if (base < XE)            { src = x;   dst = g_xh;   off = base; }
    else if (base < XE + UE)  { src = wup; dst = g_wuph; off = base - XE; }
    else                      { src = wdn; dst = g_wdnh; off = base - XE - UE; }
    float4 a = *(const float4*)(src + off);
    float4 b = *(const float4*)(src + off + 4);
    *(uint4*)(dst + off) = make_uint4(h2u(a.x, a.y), h2u(a.z, a.w),
                                      h2u(b.x, b.y), h2u(b.z, b.w));
}

// ---------------- pure-fp16 GEMM: C[M,N] = A[M,K] @ B[N,K]^T, cp.async staging ----------------
template<int BM>
__global__ void __launch_bounds__(256) gemm_h16(
        const __half* __restrict__ A, const __half* __restrict__ Bm,
        float* __restrict__ C, int M, int N, int K) {
    constexpr int MF = BM / 32;
    constexpr int NCA = BM / 64;      // A 16B chunks per thread
    __shared__ __half As[2][BM][40];
    __shared__ __half Bs[2][64][40];
    int r0 = blockIdx.y * BM, c0 = blockIdx.x * 64;
    int tid = threadIdx.x, lane = tid & 31, warp = tid >> 5;
    int wm = warp >> 2, wn = warp & 3;
    int mb = wm * (BM / 2), nb = wn * 16;
    int ln4 = lane >> 2, q4 = lane & 3;
    int lm = lane >> 3, lr = lane & 7;
    float acc[MF][2][4] = {};

    int KT = K >> 5;
    int brow = tid >> 2, bch = (tid & 3) * 8;

    // prime stage 0
    #pragma unroll
    for (int u = 0; u < NCA; u++) {
        int idx = tid + u * 256, row = idx >> 2, ch = (idx & 3) * 8;
        cp_async16((uint32_t)__cvta_generic_to_shared(&As[0][row][ch]),
                   A + (size_t)(r0 + row) * K + ch);
    }
    cp_async16((uint32_t)__cvta_generic_to_shared(&Bs[0][brow][bch]),
               Bm + (size_t)(c0 + brow) * K + bch);
    CP_COMMIT();

    for (int kt = 0; kt < KT; kt++) {
        CP_WAIT0();
        __syncthreads();
        int cur = kt & 1, nxt = cur ^ 1;
        if (kt + 1 < KT) {
            int k0 = (kt + 1) * 32;
            #pragma unroll
            for (int u = 0; u < NCA; u++) {
                int idx = tid + u * 256, row = idx >> 2, ch = (idx & 3) * 8;
                cp_async16((uint32_t)__cvta_generic_to_shared(&As[nxt][row][ch]),
                           A + (size_t)(r0 + row) * K + k0 + ch);
            }
            cp_async16((uint32_t)__cvta_generic_to_shared(&Bs[nxt][brow][bch]),
                       Bm + (size_t)(c0 + brow) * K + k0 + bch);
            CP_COMMIT();
        }
        uint32_t asb = (uint32_t)__cvta_generic_to_shared(&As[cur][0][0]);
        uint32_t bsb = (uint32_t)__cvta_generic_to_shared(&Bs[cur][0][0]);
        #pragma unroll
        for (int ks = 0; ks < 32; ks += 16) {
            uint32_t kb0, kb1, kb2, kb3;
            {
                int nrow = nb + ((lm >> 1) << 3) + lr;
                int kcol = ks + ((lm & 1) << 3);
                ldmx4(kb0, kb1, kb2, kb3, bsb + (nrow * 40 + kcol) * 2);
            }
            #pragma unroll
            for (int mf = 0; mf < MF; mf++) {
                uint32_t a0, a1, a2, a3;
                int arow = mb + mf * 16 + ((lm & 1) << 3) + lr;
                int acol = ks + ((lm >> 1) << 3);
                ldmx4(a0, a1, a2, a3, asb + (arow * 40 + acol) * 2);
                mma_f16(acc[mf][0], a0, a1, a2, a3, kb0, kb1);
                mma_f16(acc[mf][1], a0, a1, a2, a3, kb2, kb3);
            }
        }
    }

    #pragma unroll
    for (int mf = 0; mf < MF; mf++)
        #pragma unroll
        for (int nf = 0; nf < 2; nf++) {
            int row = r0 + mb + mf * 16 + ln4;
            int col = c0 + nb + nf * 8 + 2 * q4;
            C[(size_t)row * N + col]       = acc[mf][nf][0];
            C[(size_t)row * N + col + 1]   = acc[mf][nf][1];
            C[(size_t)(row + 8) * N + col]     = acc[mf][nf][2];
            C[(size_t)(row + 8) * N + col + 1] = acc[mf][nf][3];
        }
}

// ---------------- fused conv3x3+silu + qkv + gates (unchanged) ----------------
__global__ void __launch_bounds__(256) fused_mid_kernel(
        const float* __restrict__ cw,
        const float* __restrict__ qw, const float* __restrict__ kw,
        const float* __restrict__ vw,
        const float* __restrict__ igw, const float* __restrict__ igb,
        const float* __restrict__ fgw, const float* __restrict__ fgb) {
    extern __shared__ float4 smf4[];
    float4* sig4 = smf4;            // 864
    float4* sfg4 = sig4 + 864;      // 864

    int tid = threadIdx.x;
    for (int i = tid; i < 864; i += 256) { sig4[i] = ((const float4*)igw)[i]; sfg4[i] = ((const float4*)fgw)[i]; }
    __syncthreads();

    int warp = tid >> 5, lane = tid & 31;
    int bs = blockIdx.x * 8 + warp;
    int hw = bs & 1023, b = bs >> 10;
    int h = hw >> 5, w = hw & 31;

    float ai[4] = {0, 0, 0, 0}, af[4] = {0, 0, 0, 0};

    #pragma unroll
    for (int pass = 0; pass < 3; pass++) {
        int hd = pass * 32 + lane;
        if (pass == 2 && lane >= 8) break;
        int c = hd * 4;
        float4 acc = make_float4(0.f, 0.f, 0.f, 0.f);
        float4 xm = make_float4(0.f, 0.f, 0.f, 0.f);
        #pragma unroll
        for (int dh = -1; dh <= 1; dh++) {
            int hh = h + dh;
            if ((unsigned)hh >= 32u) continue;
            #pragma unroll
            for (int dw = -1; dw <= 1; dw++) {
                int ww = w + dw;
                if ((unsigned)ww >= 32u) continue;
                float4 xv = *(const float4*)&g_y[(size_t)(b * S_LEN + hh * 32 + ww) * (2 * INNER) + c];
                float4 wv = __ldg((const float4*)&cw[((dh + 1) * 3 + (dw + 1)) * INNER + c]);
                acc.x += xv.x * wv.x; acc.y += xv.y * wv.y;
                acc.z += xv.z * wv.z; acc.w += xv.w * wv.w;
                if (dh == 0 && dw == 0) xm = xv;
            }
        }
        float4 xa;
        xa.x = acc.x / (1.f + expf(-acc.x));
        xa.y = acc.y / (1.f + expf(-acc.y));
        xa.z = acc.z / (1.f + expf(-acc.z));
        xa.w = acc.w / (1.f + expf(-acc.w));
        *(float4*)&g_xa[(size_t)bs * INNER + c] = xa;

        float qo[4], ko[4], vo[4];
        #pragma unroll
        for (int o = 0; o < 4; o++) {
            float4 wq = __ldg((const float4*)&qw[hd * 16 + o * 4]);
            float4 wk = __ldg((const float4*)&kw[hd * 16 + o * 4]);
            float4 wv2 = __ldg((const float4*)&vw[hd * 16 + o * 4]);
            qo[o] = xa.x * wq.x + xa.y * wq.y + xa.z * wq.z + xa.w * wq.w;
            ko[o] = xa.x * wk.x + xa.y * wk.y + xa.z * wk.z + xa.w * wk.w;
            vo[o] = xm.x * wv2.x + xm.y * wv2.y + xm.z * wv2.z + xm.w * wv2.w;
        }
        uint2 qu = make_uint2(h2u(qo[0], qo[1]), h2u(qo[2], qo[3]));
        uint2 ku = make_uint2(h2u(ko[0], ko[1]), h2u(ko[2], ko[3]));
        uint2 vu = make_uint2(h2u(vo[0], vo[1]), h2u(vo[2], vo[3]));
        *(uint2*)&g_q[(size_t)bs * INNER + c] = qu;
        *(uint2*)&g_k[(size_t)bs * INNER + c] = ku;
        *(uint2*)&g_v[(size_t)bs * INNER + c] = vu;

        #pragma unroll
        for (int n = 0; n < 4; n++) {
            float4 wv4;
            wv4 = sig4[n * 216 + hd];
            ai[n] += qo[0] * wv4.x + qo[1] * wv4.y + qo[2] * wv4.z + qo[3] * wv4.w;
            wv4 = sig4[n * 216 + 72 + hd];
            ai[n] += ko[0] * wv4.x + ko[1] * wv4.y + ko[2] * wv4.z + ko[3] * wv4.w;
            wv4 = sig4[n * 216 + 144 + hd];
            ai[n] += vo[0] * wv4.x + vo[1] * wv4.y + vo[2] * wv4.z + vo[3] * wv4.w;
            wv4 = sfg4[n * 216 + hd];
            af[n] += qo[0] * wv4.x + qo[1] * wv4.y + qo[2] * wv4.z + qo[3] * wv4.w;
            wv4 = sfg4[n * 216 + 72 + hd];
            af[n] += ko[0] * wv4.x + ko[1] * wv4.y + ko[2] * wv4.z + ko[3] * wv4.w;
            wv4 = sfg4[n * 216 + 144 + hd];
            af[n] += vo[0] * wv4.x + vo[1] * wv4.y + vo[2] * wv4.z + vo[3] * wv4.w;
        }
    }
    #pragma unroll
    for (int off = 16; off; off >>= 1) {
        #pragma unroll
        for (int n = 0; n < 4; n++) {
            ai[n] += __shfl_xor_sync(0xffffffffu, ai[n], off);
            af[n] += __shfl_xor_sync(0xffffffffu, af[n], off);
        }
    }
    if (lane == 0) {
        int b2 = bs >> 10, s = bs & 1023;
        #pragma unroll
        for (int n = 0; n < 4; n++) {
            g_ig[(size_t)(b2 * 4 + n) * S_LEN + s] = ai[n] + igb[n];
            g_fg[(size_t)(b2 * 4 + n) * S_LEN + s] = af[n] + fgb[n];
        }
    }
}

// ---------------- scan: stores exp(m) in g_m ----------------
__global__ void scan_kernel() {
    __shared__ float wbuf[32];
    int t = threadIdx.x, lane = t & 31, wid = t >> 5;
    int base = blockIdx.x * S_LEN;
    float fgv = g_fg[base + t];
    float lf = fminf(fgv, 0.f) - log1pf(expf(-fabsf(fgv)));
    float v = lf;
    #pragma unroll
    for (int o = 1; o < 32; o <<= 1) {
        float u = __shfl_up_sync(0xffffffffu, v, o);
        if (lane >= o) v += u;
    }
    if (lane == 31) wbuf[wid] = v;
    __syncthreads();
    if (wid == 0) {
        float s = wbuf[lane];
        #pragma unroll
        for (int o = 1; o < 32; o <<= 1) {
            float u = __shfl_up_sync(0xffffffffu, s, o);
            if (lane >= o) s += u;
        }
        wbuf[lane] = s;
    }
    __syncthreads();
    float lfc = v + (wid ? wbuf[wid - 1] : 0.f);
    float m = g_ig[base + t] - lfc;
    __syncthreads();
    float mx = m;
    #pragma unroll
    for (int o = 1; o < 32; o <<= 1) {
        float u = __shfl_up_sync(0xffffffffu, mx, o);
        if (lane >= o) mx = fmaxf(mx, u);
    }
    if (lane == 31) wbuf[wid] = mx;
    __syncthreads();
    if (wid == 0) {
        float s = wbuf[lane];
        #pragma unroll
        for (int o = 1; o < 32; o <<= 1) {
            float u = __shfl_up_sync(0xffffffffu, s, o);
            if (lane >= o) s = fmaxf(s, u);
        }
        wbuf[lane] = s;
    }
    __syncthreads();
    float Mv = wid ? fmaxf(mx, wbuf[wid - 1]) : mx;
    g_m [base + t] = expf(m);
    g_Mx[base + t] = Mv;
    g_d0[base + t] = expf(-lfc - Mv);
}

// ---------------- mLSTM attention v9 (unchanged from round 15) ----------------
#define KVSLOT 2816   // u32 per slab: 64 rows * 44 u32 (88 halves)
__global__ void __launch_bounds__(256, 2) attn_kernel(const float* __restrict__ normw,
                                                      const float* __restrict__ skipw) {
    extern __shared__ uint32_t smu[];
    uint32_t* Ks = smu;
    uint32_t* Vs = smu + 2 * KVSLOT;
    float* wms = (float*)(smu + 4 * KVSLOT);

    int bn = blockIdx.y;
    int b = bn >> 2, n = bn & 3;
    int tid = threadIdx.x, lane = tid & 31, warp = tid >> 5;
    int wm = warp & 3, wn = warp >> 2;
    int ln4 = lane >> 2, q4 = lane & 3;
    int r0 = wm * 16;
    int cb0 = wn * 32;
    int rr = r0 + ln4;
    const float scale = 0.11785113019775793f;
    const unsigned FULL = 0xffffffffu;

    uint32_t smbase = (uint32_t)__cvta_generic_to_shared(smu);

    int sOffG[5], sOffS[5];
    bool sIsV[5], sOK[5];
    #pragma unroll
    for (int u = 0; u < 5; u++) {
        int i = tid + u * 256;
        sOK[u]  = (i < 1152);
        sIsV[u] = (i >= 576);
        int j = sIsV[u] ? i - 576 : i;
        int r = j / 9, ch = j - r * 9;
        sOffG[u] = r * INNER + ch * 8;
        sOffS[u] = r * 44 + ch * 4;
    }

    int lm = lane >> 3, lr = lane & 7;

    #pragma unroll 1
    for (int sub = 0; sub < 2; sub++) {
        int R = sub == 0 ? (gridDim.x * 2 - 1 - blockIdx.x) : blockIdx.x;
        int S0 = R * 64;

        if (sub) __syncthreads();

        for (int i = tid; i < 2048; i += 256) {
            int slab = i >> 9, rem = i & 511;
            int r = rem >> 3, cc = 36 + (rem & 7);
            uint32_t val = (slab >= 2 && cc == 36) ? 0x00003C00u : 0u;
            smu[slab * KVSLOT + r * 44 + cc] = val;
        }
        float w0 = expf(-g_Mx[(size_t)bn * S_LEN + S0 + rr]) * scale;
        float w1 = expf(-g_Mx[(size_t)bn * S_LEN + S0 + rr + 8]) * scale;
        float d00 = g_d0[(size_t)bn * S_LEN + S0 + rr];
        float d01 = g_d0[(size_t)bn * S_LEN + S0 + rr + 8];
        if (tid < 64) wms[tid] = g_m[(size_t)bn * S_LEN + tid];

        const __half* kb = g_k + (size_t)(b * S_LEN) * INNER + n * 72;
        const __half* vb = g_v + (size_t)(b * S_LEN) * INNER + n * 72;

        #pragma unroll
        for (int u = 0; u < 5; u++) {
            if (!sOK[u]) continue;
            const __half* src = (sIsV[u] ? vb : kb) + sOffG[u];
            uint32_t* dst = (sIsV[u] ? Vs : Ks) + sOffS[u];
            cp_async16((uint32_t)__cvta_generic_to_shared(dst), src);
        }
        CP_COMMIT();

        uint32_t qf[5][4];
        {
            const __half* q0 = g_q + (size_t)(b * S_LEN + S0 + r0 + ln4) * INNER + n * 72;
            const __half* q1 = q0 + 8 * INNER;
            #pragma unroll
            for (int s = 0; s < 5; s++) {
                int c = s * 16 + 2 * q4;
                qf[s][0] = *(const uint32_t*)(q0 + c);
                qf[s][1] = *(const uint32_t*)(q1 + c);
                int c2 = c + 8;
                if (s < 4) {
                    qf[s][2] = *(const uint32_t*)(q0 + c2);
                    qf[s][3] = *(const uint32_t*)(q1 + c2);
                } else {
                    qf[s][2] = 0u; qf[s][3] = 0u;
                }
            }
        }
        __syncthreads();

        float o[10][4] = {};

        for (int ct = 0; ct <= R; ct++) {
            CP_WAIT0();
            __syncthreads();
            int cur = ct & 1, nxt = cur ^ 1;
            if (ct < R) {
                kb += 64 * INNER;
                vb += 64 * INNER;
                uint32_t* Kd = Ks + nxt * KVSLOT;
                uint32_t* Vd = Vs + nxt * KVSLOT;
                #pragma unroll
                for (int u = 0; u < 5; u++) {
                    if (!sOK[u]) continue;
                    const __half* src = (sIsV[u] ? vb : kb) + sOffG[u];
                    uint32_t* dst = (sIsV[u] ? Vd : Kd) + sOffS[u];
                    cp_async16((uint32_t)__cvta_generic_to_shared(dst), src);
                }
                CP_COMMIT();
                if (tid < 64) wms[nxt * 64 + tid] = g_m[(size_t)bn * S_LEN + (ct + 1) * 64 + tid];
            }
            uint32_t kbase = smbase + (cur * KVSLOT) * 4;
            uint32_t vbase = smbase + ((2 + cur) * KVSLOT) * 4;
            const float* wmc = wms + cur * 64;

            float pc[4][4] = {};
            #pragma unroll
            for (int s = 0; s < 5; s++) {
                #pragma unroll
                for (int p = 0; p < 2; p++) {
                    int nrow = cb0 + p * 16 + ((lm >> 1) << 3) + lr;
                    int kcol = s * 16 + ((lm & 1) << 3);
                    uint32_t addr = kbase + nrow * 176 + kcol * 2;
                    uint32_t kb0, kb1, kb2, kb3;
                    ldmx4(kb0, kb1, kb2, kb3, addr);
                    if (s < 4) {
                        mma_f16(pc[2 * p],     qf[s][0], qf[s][1], qf[s][2], qf[s][3], kb0, kb1);
                        mma_f16(pc[2 * p + 1], qf[s][0], qf[s][1], qf[s][2], qf[s][3], kb2, kb3);
                    } else {
                        mma_f16_k8(pc[2 * p],     qf[s][0], qf[s][1], kb0);
                        mma_f16_k8(pc[2 * p + 1], qf[s][0], qf[s][1], kb2);
                    }
                }
            }

            bool diag = (ct == R);
            uint32_t pa[2][4];
            #pragma unroll
            for (int p = 0; p < 2; p++) {
                #pragma unroll
                for (int hh = 0; hh < 2; hh++) {
                    int nf = 2 * p + hh;
                    int c0 = cb0 + nf * 8 + 2 * q4;
                    float wc0 = wmc[c0], wc1 = wmc[c0 + 1];
                    float v00 = pc[nf][0] * w0 * wc0;
                    float v01 = pc[nf][1] * w0 * wc1;
                    float v10 = pc[nf][2] * w1 * wc0;
                    float v11 = pc[nf][3] * w1 * wc1;
                    if (diag) {
                        if (c0 > rr)         v00 = 0.f;
                        if (c0 + 1 > rr)     v01 = 0.f;
                        if (c0 > rr + 8)     v10 = 0.f;
                        if (c0 + 1 > rr + 8) v11 = 0.f;
                    }
                    pa[p][hh * 2 + 0] = h2u(v00, v01);
                    pa[p][hh * 2 + 1] = h2u(v10, v11);
                }
            }

            #pragma unroll
            for (int p = 0; p < 2; p++) {
                int kb2 = cb0 + p * 16;
                #pragma unroll
                for (int pf = 0; pf < 5; pf++) {
                    int vrow = kb2 + ((lm & 1) << 3) + lr;
                    int vcol = pf * 16 + ((lm >> 1) << 3);
                    uint32_t addr = vbase + vrow * 176 + vcol * 2;
                    uint32_t vb0, vb1, vb2, vb3;
                    ldmx4t(vb0, vb1, vb2, vb3, addr);
                    mma_f16(o[2 * pf],     pa[p][0], pa[p][1], pa[p][2], pa[p][3], vb0, vb1);
                    mma_f16(o[2 * pf + 1], pa[p][0], pa[p][1], pa[p][2], pa[p][3], vb2, vb3);
                }
            }
        }

        __syncthreads();
        float* OsB = (float*)Ks;
        if (wn == 1) {
            #pragma unroll
            for (int nf = 0; nf < 9; nf++) {
                int c = nf * 8 + 2 * q4;
                OsB[rr * 76 + c]           = o[nf][0];
                OsB[rr * 76 + c + 1]       = o[nf][1];
                OsB[(rr + 8) * 76 + c]     = o[nf][2];
                OsB[(rr + 8) * 76 + c + 1] = o[nf][3];
            }
            if (q4 == 0) {
                OsB[rr * 76 + 72]       = o[9][0];
                OsB[(rr + 8) * 76 + 72] = o[9][2];
            }
        }
        __syncthreads();
        float* Of = (float*)Vs;
        if (wn == 0) {
            float p0 = __shfl_sync(FULL, o[9][0], lane & 28);
            float p1 = __shfl_sync(FULL, o[9][2], lane & 28);
            float rs0 = p0 + OsB[rr * 76 + 72];
            float rs1 = p1 + OsB[(rr + 8) * 76 + 72];
            float inv0 = 1.f / (fmaxf(fabsf(rs0), d00) + 1e-6f);
            float inv1 = 1.f / (fmaxf(fabsf(rs1), d01) + 1e-6f);
            #pragma unroll
            for (int nf = 0; nf < 9; nf++) {
                int c = nf * 8 + 2 * q4;
                Of[rr * 76 + c]           = (o[nf][0] + OsB[rr * 76 + c])           * inv0;
                Of[rr * 76 + c + 1]       = (o[nf][1] + OsB[rr * 76 + c + 1])       * inv0;
                Of[(rr + 8) * 76 + c]     = (o[nf][2] + OsB[(rr + 8) * 76 + c])     * inv1;
                Of[(rr + 8) * 76 + c + 1] = (o[nf][3] + OsB[(rr + 8) * 76 + c + 1]) * inv1;
            }
        }
        __syncthreads();

        float nw0 = normw[n * 72 + lane];
        float sk0 = skipw[n * 72 + lane];
        float nw1 = normw[n * 72 + 32 + lane];
        float sk1 = skipw[n * 72 + 32 + lane];
        float nw2 = 0.f, sk2 = 0.f;
        if (lane < 8) { nw2 = normw[n * 72 + 64 + lane]; sk2 = skipw[n * 72 + 64 + lane]; }

        #pragma unroll
        for (int r8 = 0; r8 < 8; r8++) {
            int r = warp * 8 + r8;
            float h0 = Of[r * 76 + lane];
            float h1 = Of[r * 76 + 32 + lane];
            float h2 = (lane < 8) ? Of[r * 76 + 64 + lane] : 0.f;
            float psum = h0 + h1 + h2;
            #pragma unroll
            for (int off = 16; off; off >>= 1) psum += __shfl_xor_sync(FULL, psum, off);
            float mean = psum * (1.f / 72.f);
            float dv0 = h0 - mean, dv1 = h1 - mean, dv2 = h2 - mean;
            float pss = dv0 * dv0 + dv1 * dv1 + ((lane < 8) ? dv2 * dv2 : 0.f);
            #pragma unroll
            for (int off = 16; off; off >>= 1) pss += __shfl_xor_sync(FULL, pss, off);
            float rstd = rsqrtf(pss * (1.f / 72.f) + 1e-5f);

            size_t row  = (size_t)(b * S_LEN + S0 + r) * INNER;
            size_t zrow = (size_t)(b * S_LEN + S0 + r) * (2 * INNER) + INNER;
            {
                int c = n * 72 + lane;
                float z = g_y[zrow + c];
                float val = dv0 * rstd * nw0 + sk0 * g_xa[row + c];
                g_hs[row + c] = __float2half_rn(val * (z / (1.f + expf(-z))));
            }
            {
                int c = n * 72 + 32 + lane;
                float z = g_y[zrow + c];
                float val = dv1 * rstd * nw1 + sk1 * g_xa[row + c];
                g_hs[row + c] = __float2half_rn(val * (z / (1.f + expf(-z))));
            }
            if (lane < 8) {
                int c = n * 72 + 64 + lane;
                float z = g_y[zrow + c];
                float val = dv2 * rstd * nw2 + sk2 * g_xa[row + c];
                g_hs[row + c] = __float2half_rn(val * (z / (1.f + expf(-z))));
            }
        }
    }
}

// ---------------- launch ----------------
extern "C" void kernel_launch(void* const* d_in, const int* in_sizes, int n_in,
                              void* d_out, int out_size) {
    const float* x           = (const float*)d_in[0];
    const float* proj_up_w   = (const float*)d_in[1];
    const float* q_w         = (const float*)d_in[2];
    const float* k_w         = (const float*)d_in[3];
    const float* v_w         = (const float*)d_in[4];
    const float* conv_w      = (const float*)d_in[5];
    const float* ig_w        = (const float*)d_in[6];
    const float* ig_b        = (const float*)d_in[7];
    const float* fg_w        = (const float*)d_in[8];
    const float* fg_b        = (const float*)d_in[9];
    const float* norm_w      = (const float*)d_in[10];
    const float* skip        = (const float*)d_in[11];
    const float* proj_down_w = (const float*)d_in[12];
    float* out = (float*)d_out;

    float* py;
    __half *phs, *pxh, *pwuph, *pwdnh;
    cudaGetSymbolAddress((void**)&py,    g_y);
    cudaGetSymbolAddress((void**)&phs,   g_hs);
    cudaGetSymbolAddress((void**)&pxh,   g_xh);
    cudaGetSymbolAddress((void**)&pwuph, g_wuph);
    cudaGetSymbolAddress((void**)&pwdnh, g_wdnh);

    // 0) fp32 -> fp16 converts (x, W_up, W_down)
    cvt_kernel<<<(XE + UE + DE) / 8 / 256, 256>>>(x, proj_up_w, proj_down_w);

    // 1) proj_up (pure fp16, cp.async)
    gemm_h16<128><<<dim3(576 / 64, BS_TOT / 128), 256>>>(pxh, pwuph, py, BS_TOT, 2 * INNER, DIMX);

    // 2) fused conv+silu+qkv+gates
    size_t smem_mid = (size_t)2 * 864 * 16;
    fused_mid_kernel<<<BS_TOT / 8, 256, smem_mid>>>(conv_w, q_w, k_w, v_w,
                                                    ig_w, ig_b, fg_w, fg_b);

    // 3) scan (stores exp(m))
    scan_kernel<<<32, S_LEN>>>();

    // 4) attention + LN + skip + silu(z): 8 balanced pairs x 32 bn
    size_t smem_attn = (size_t)(4 * KVSLOT + 128) * 4;
    cudaFuncSetAttribute(attn_kernel, cudaFuncAttributeMaxDynamicSharedMemorySize, (int)smem_attn);
    attn_kernel<<<dim3(8, 32), 256, smem_attn>>>(norm_w, skip);

    // 5) proj_down (pure fp16, cp.async)
    gemm_h16<64><<<dim3(DIMX / 64, BS_TOT / 64), 256>>>(phs, pwdnh, out, BS_TOT, DIMX, INNER);
}

// round 17
// speedup vs baseline: 1.0727x; 1.0234x over previous
#include <cuda_runtime.h>
#include <cuda_fp16.h>
#include <math.h>
#include <stdint.h>

#define S_LEN 1024
#define BATCH 8
#define BS_TOT 8192          // B*S
#define INNER 288
#define DIMX 192
#define NHQ 72
#define NHM 4
#define DHM 72

// ---------------- scratch (static __device__, no allocations) ----------------
__device__ float  g_z [BS_TOT * INNER];      // z half of proj_up output (fp32)
__device__ __align__(256) __half g_xmh[BS_TOT * INNER];  // x_m half (fp16)
__device__ float  g_xa[BS_TOT * INNER];      // silu(conv(x_m))
__device__ __align__(256) __half g_q [BS_TOT * INNER];  // fp16 (RNE)
__device__ __align__(256) __half g_k [BS_TOT * INNER];  // fp16 (RNE)
__device__ __align__(256) __half g_v [BS_TOT * INNER];  // fp16 (RNE)
__device__ float  g_ig[32 * S_LEN];          // [b*4+n][s]
__device__ float  g_fg[32 * S_LEN];
__device__ float  g_m [32 * S_LEN];          // exp(ig - lfc)  (pre-exponentiated)
__device__ float  g_Mx[32 * S_LEN];          // prefix max of m
__device__ float  g_d0[32 * S_LEN];          // exp(-lfc - M)
__device__ __align__(256) __half g_hs[BS_TOT * INNER];  // h_state (fp16)
// pre-converted fp16 GEMM operands
__device__ __align__(256) __half g_xh  [BS_TOT * DIMX];   // x fp16
__device__ __align__(256) __half g_wuph[2 * INNER * DIMX];// W_up fp16
__device__ __align__(256) __half g_wdnh[DIMX * INNER];    // W_down fp16

#define XE (BS_TOT * DIMX)        // 1572864
#define UE (2 * INNER * DIMX)     // 110592
#define DE (DIMX * INNER)         // 55296

// ---------------- helpers ----------------
__device__ __forceinline__ void mma_f16(float c[4], uint32_t a0, uint32_t a1,
                                        uint32_t a2, uint32_t a3,
                                        uint32_t b0, uint32_t b1) {
    asm volatile(
        "mma.sync.aligned.m16n8k16.row.col.f32.f16.f16.f32 "
        "{%0,%1,%2,%3}, {%4,%5,%6,%7}, {%8,%9}, {%0,%1,%2,%3};"
        : "+f"(c[0]), "+f"(c[1]), "+f"(c[2]), "+f"(c[3])
        : "r"(a0), "r"(a1), "r"(a2), "r"(a3), "r"(b0), "r"(b1));
}

__device__ __forceinline__ void mma_f16_k8(float c[4], uint32_t a0, uint32_t a1,
                                           uint32_t b0) {
    asm volatile(
        "mma.sync.aligned.m16n8k8.row.col.f32.f16.f16.f32 "
        "{%0,%1,%2,%3}, {%4,%5}, {%6}, {%0,%1,%2,%3};"
        : "+f"(c[0]), "+f"(c[1]), "+f"(c[2]), "+f"(c[3])
        : "r"(a0), "r"(a1), "r"(b0));
}

__device__ __forceinline__ void ldmx4(uint32_t& r0, uint32_t& r1, uint32_t& r2,
                                      uint32_t& r3, uint32_t addr) {
    asm volatile("ldmatrix.sync.aligned.m8n8.x4.shared.b16 {%0,%1,%2,%3}, [%4];"
                 : "=r"(r0), "=r"(r1), "=r"(r2), "=r"(r3) : "r"(addr));
}

__device__ __forceinline__ void ldmx4t(uint32_t& r0, uint32_t& r1, uint32_t& r2,
                                       uint32_t& r3, uint32_t addr) {
    asm volatile("ldmatrix.sync.aligned.m8n8.x4.trans.shared.b16 {%0,%1,%2,%3}, [%4];"
                 : "=r"(r0), "=r"(r1), "=r"(r2), "=r"(r3) : "r"(addr));
}

__device__ __forceinline__ uint32_t h2u(float a, float b) {
    __half2 h = __floats2half2_rn(a, b);
    return *reinterpret_cast<uint32_t*>(&h);
}

__device__ __forceinline__ void cp_async16(uint32_t dst, const void* src) {
    asm volatile("cp.async.cg.shared.global [%0], [%1], 16;" :: "r"(dst), "l"(src));
}
#define CP_COMMIT() asm volatile("cp.async.commit_group;" ::: "memory")
#define CP_WAIT0()  asm volatile("cp.async.wait_group 0;" ::: "memory")

// ---------------- fp32 -> fp16 convert (x, W_up, W_down) ----------------
__global__ void __launch_bounds__(256) cvt_kernel(const float* __restrict__ x,
                                                  const float* __restrict__ wup,
                                                  const float* __restrict__ wdn) {
    int base = (blockIdx.x * 256 + threadIdx.x) * 8;
    const float* src;
    __half* dst;
    int off;
    if (base < XE)            { src = x;   dst = g_xh;   off = base; }
    else if (base < XE + UE)  { src = wup; dst = g_wuph; off = base - XE; }
    else                      { src = wdn; dst = g_wdnh; off = base - XE - UE; }
    float4 a = *(const float4*)(src + off);
    float4 b = *(const float4*)(src + off + 4);
    *(uint4*)(dst + off) = make_uint4(h2u(a.x, a.y), h2u(a.z, a.w),
                                      h2u(b.x, b.y), h2u(b.z, b.w));
}

// ---------------- pure-fp16 GEMM: C[M,N] = A[M,K] @ B[N,K]^T, cp.async staging ----------------
// MODE 0: plain fp32 C.  MODE 1 (proj_up): col<INNER -> g_xmh fp16; col>=INNER -> g_z fp32.
template<int BM, int MODE>
__global__ void __launch_bounds__(256) gemm_h16(
        const __half* __restrict__ A, const __half* __restrict__ Bm,
        float* __restrict__ C, int M, int N, int K) {
    constexpr int MF = BM / 32;
    constexpr int NCA = BM / 64;      // A 16B chunks per thread
    __shared__ __half As[2][BM][40];
    __shared__ __half Bs[2][64][40];
    int r0 = blockIdx.y * BM, c0 = blockIdx.x * 64;
    int tid = threadIdx.x, lane = tid & 31, warp = tid >> 5;
    int wm = warp >> 2, wn = warp & 3;
    int mb = wm * (BM / 2), nb = wn * 16;
    int ln4 = lane >> 2, q4 = lane & 3;
    int lm = lane >> 3, lr = lane & 7;
    float acc[MF][2][4] = {};

    int KT = K >> 5;
    int brow = tid >> 2, bch = (tid & 3) * 8;

    #pragma unroll
    for (int u = 0; u < NCA; u++) {
        int idx = tid + u * 256, row = idx >> 2, ch = (idx & 3) * 8;
        cp_async16((uint32_t)__cvta_generic_to_shared(&As[0][row][ch]),
                   A + (size_t)(r0 + row) * K + ch);
    }
    cp_async16((uint32_t)__cvta_generic_to_shared(&Bs[0][brow][bch]),
               Bm + (size_t)(c0 + brow) * K + bch);
    CP_COMMIT();

    for (int kt = 0; kt < KT; kt++) {
        CP_WAIT0();
        __syncthreads();
        int cur = kt & 1, nxt = cur ^ 1;
        if (kt + 1 < KT) {
            int k0 = (kt + 1) * 32;
            #pragma unroll
            for (int u = 0; u < NCA; u++) {
                int idx = tid + u * 256, row = idx >> 2, ch = (idx & 3) * 8;
                cp_async16((uint32_t)__cvta_generic_to_shared(&As[nxt][row][ch]),
                           A + (size_t)(r0 + row) * K + k0 + ch);
            }
            cp_async16((uint32_t)__cvta_generic_to_shared(&Bs[nxt][brow][bch]),
                       Bm + (size_t)(c0 + brow) * K + k0 + bch);
            CP_COMMIT();
        }
        uint32_t asb = (uint32_t)__cvta_generic_to_shared(&As[cur][0][0]);
        uint32_t bsb = (uint32_t)__cvta_generic_to_shared(&Bs[cur][0][0]);
        #pragma unroll
        for (int ks = 0; ks < 32; ks += 16) {
            uint32_t kb0, kb1, kb2, kb3;
            {
                int nrow = nb + ((lm >> 1) << 3) + lr;
                int kcol = ks + ((lm & 1) << 3);
                ldmx4(kb0, kb1, kb2, kb3, bsb + (nrow * 40 + kcol) * 2);
            }
            #pragma unroll
            for (int mf = 0; mf < MF; mf++) {
                uint32_t a0, a1, a2, a3;
                int arow = mb + mf * 16 + ((lm & 1) << 3) + lr;
                int acol = ks + ((lm >> 1) << 3);
                ldmx4(a0, a1, a2, a3, asb + (arow * 40 + acol) * 2);
                mma_f16(acc[mf][0], a0, a1, a2, a3, kb0, kb1);
                mma_f16(acc[mf][1], a0, a1, a2, a3, kb2, kb3);
            }
        }
    }

    #pragma unroll
    for (int mf = 0; mf < MF; mf++)
        #pragma unroll
        for (int nf = 0; nf < 2; nf++) {
            int row = r0 + mb + mf * 16 + ln4;
            int col = c0 + nb + nf * 8 + 2 * q4;
            if (MODE == 0) {
                C[(size_t)row * N + col]       = acc[mf][nf][0];
                C[(size_t)row * N + col + 1]   = acc[mf][nf][1];
                C[(size_t)(row + 8) * N + col]     = acc[mf][nf][2];
                C[(size_t)(row + 8) * N + col + 1] = acc[mf][nf][3];
            } else {
                if (col < INNER) {
                    *(uint32_t*)&g_xmh[(size_t)row * INNER + col] =
                        h2u(acc[mf][nf][0], acc[mf][nf][1]);
                    *(uint32_t*)&g_xmh[(size_t)(row + 8) * INNER + col] =
                        h2u(acc[mf][nf][2], acc[mf][nf][3]);
                } else {
                    int zc = col - INNER;
                    g_z[(size_t)row * INNER + zc]           = acc[mf][nf][0];
                    g_z[(size_t)row * INNER + zc + 1]       = acc[mf][nf][1];
                    g_z[(size_t)(row + 8) * INNER + zc]     = acc[mf][nf][2];
                    g_z[(size_t)(row + 8) * INNER + zc + 1] = acc[mf][nf][3];
                }
            }
        }
}

// ---------------- fused conv3x3+silu + qkv + gates (x_m read as fp16) ----------------
__global__ void __launch_bounds__(256) fused_mid_kernel(
        const float* __restrict__ cw,
        const float* __restrict__ qw, const float* __restrict__ kw,
        const float* __restrict__ vw,
        const float* __restrict__ igw, const float* __restrict__ igb,
        const float* __restrict__ fgw, const float* __restrict__ fgb) {
    extern __shared__ float4 smf4[];
    float4* sig4 = smf4;            // 864
    float4* sfg4 = sig4 + 864;      // 864

    int tid = threadIdx.x;
    for (int i = tid; i < 864; i += 256) { sig4[i] = ((const float4*)igw)[i]; sfg4[i] = ((const float4*)fgw)[i]; }
    __syncthreads();

    int warp = tid >> 5, lane = tid & 31;
    int bs = blockIdx.x * 8 + warp;
    int hw = bs & 1023, b = bs >> 10;
    int h = hw >> 5, w = hw & 31;

    float ai[4] = {0, 0, 0, 0}, af[4] = {0, 0, 0, 0};

    #pragma unroll
    for (int pass = 0; pass < 3; pass++) {
        int hd = pass * 32 + lane;
        if (pass == 2 && lane >= 8) break;
        int c = hd * 4;
        float4 acc = make_float4(0.f, 0.f, 0.f, 0.f);
        float4 xm = make_float4(0.f, 0.f, 0.f, 0.f);
        #pragma unroll
        for (int dh = -1; dh <= 1; dh++) {
            int hh = h + dh;
            if ((unsigned)hh >= 32u) continue;
            #pragma unroll
            for (int dw = -1; dw <= 1; dw++) {
                int ww = w + dw;
                if ((unsigned)ww >= 32u) continue;
                uint2 raw = *(const uint2*)&g_xmh[(size_t)(b * S_LEN + hh * 32 + ww) * INNER + c];
                float2 f01 = __half22float2(*(const __half2*)&raw.x);
                float2 f23 = __half22float2(*(const __half2*)&raw.y);
                float4 wv = __ldg((const float4*)&cw[((dh + 1) * 3 + (dw + 1)) * INNER + c]);
                acc.x += f01.x * wv.x; acc.y += f01.y * wv.y;
                acc.z += f23.x * wv.z; acc.w += f23.y * wv.w;
                if (dh == 0 && dw == 0) xm = make_float4(f01.x, f01.y, f23.x, f23.y);
            }
        }
        float4 xa;
        xa.x = acc.x / (1.f + expf(-acc.x));
        xa.y = acc.y / (1.f + expf(-acc.y));
        xa.z = acc.z / (1.f + expf(-acc.z));
        xa.w = acc.w / (1.f + expf(-acc.w));
        *(float4*)&g_xa[(size_t)bs * INNER + c] = xa;

        float qo[4], ko[4], vo[4];
        #pragma unroll
        for (int o = 0; o < 4; o++) {
            float4 wq = __ldg((const float4*)&qw[hd * 16 + o * 4]);
            float4 wk = __ldg((const float4*)&kw[hd * 16 + o * 4]);
            float4 wv2 = __ldg((const float4*)&vw[hd * 16 + o * 4]);
            qo[o] = xa.x * wq.x + xa.y * wq.y + xa.z * wq.z + xa.w * wq.w;
            ko[o] = xa.x * wk.x + xa.y * wk.y + xa.z * wk.z + xa.w * wk.w;
            vo[o] = xm.x * wv2.x + xm.y * wv2.y + xm.z * wv2.z + xm.w * wv2.w;
        }
        uint2 qu = make_uint2(h2u(qo[0], qo[1]), h2u(qo[2], qo[3]));
        uint2 ku = make_uint2(h2u(ko[0], ko[1]), h2u(ko[2], ko[3]));
        uint2 vu = make_uint2(h2u(vo[0], vo[1]), h2u(vo[2], vo[3]));
        *(uint2*)&g_q[(size_t)bs * INNER + c] = qu;
        *(uint2*)&g_k[(size_t)bs * INNER + c] = ku;
        *(uint2*)&g_v[(size_t)bs * INNER + c] = vu;

        #pragma unroll
        for (int n = 0; n < 4; n++) {
            float4 wv4;
            wv4 = sig4[n * 216 + hd];
            ai[n] += qo[0] * wv4.x + qo[1] * wv4.y + qo[2] * wv4.z + qo[3] * wv4.w;
            wv4 = sig4[n * 216 + 72 + hd];
            ai[n] += ko[0] * wv4.x + ko[1] * wv4.y + ko[2] * wv4.z + ko[3] * wv4.w;
            wv4 = sig4[n * 216 + 144 + hd];
            ai[n] += vo[0] * wv4.x + vo[1] * wv4.y + vo[2] * wv4.z + vo[3] * wv4.w;
            wv4 = sfg4[n * 216 + hd];
            af[n] += qo[0] * wv4.x + qo[1] * wv4.y + qo[2] * wv4.z + qo[3] * wv4.w;
            wv4 = sfg4[n * 216 + 72 + hd];
            af[n] += ko[0] * wv4.x + ko[1] * wv4.y + ko[2] * wv4.z + ko[3] * wv4.w;
            wv4 = sfg4[n * 216 + 144 + hd];
            af[n] += vo[0] * wv4.x + vo[1] * wv4.y + vo[2] * wv4.z + vo[3] * wv4.w;
        }
    }
    #pragma unroll
    for (int off = 16; off; off >>= 1) {
        #pragma unroll
        for (int n = 0; n < 4; n++) {
            ai[n] += __shfl_xor_sync(0xffffffffu, ai[n], off);
            af[n] += __shfl_xor_sync(0xffffffffu, af[n], off);
        }
    }
    if (lane == 0) {
        int b2 = bs >> 10, s = bs & 1023;
        #pragma unroll
        for (int n = 0; n < 4; n++) {
            g_ig[(size_t)(b2 * 4 + n) * S_LEN + s] = ai[n] + igb[n];
            g_fg[(size_t)(b2 * 4 + n) * S_LEN + s] = af[n] + fgb[n];
        }
    }
}

// ---------------- scan: stores exp(m) in g_m ----------------
__global__ void scan_kernel() {
    __shared__ float wbuf[32];
    int t = threadIdx.x, lane = t & 31, wid = t >> 5;
    int base = blockIdx.x * S_LEN;
    float fgv = g_fg[base + t];
    float lf = fminf(fgv, 0.f) - log1pf(expf(-fabsf(fgv)));
    float v = lf;
    #pragma unroll
    for (int o = 1; o < 32; o <<= 1) {
        float u = __shfl_up_sync(0xffffffffu, v, o);
        if (lane >= o) v += u;
    }
    if (lane == 31) wbuf[wid] = v;
    __syncthreads();
    if (wid == 0) {
        float s = wbuf[lane];
        #pragma unroll
        for (int o = 1; o < 32; o <<= 1) {
            float u = __shfl_up_sync(0xffffffffu, s, o);
            if (lane >= o) s += u;
        }
        wbuf[lane] = s;
    }
    __syncthreads();
    float lfc = v + (wid ? wbuf[wid - 1] : 0.f);
    float m = g_ig[base + t] - lfc;
    __syncthreads();
    float mx = m;
    #pragma unroll
    for (int o = 1; o < 32; o <<= 1) {
        float u = __shfl_up_sync(0xffffffffu, mx, o);
        if (lane >= o) mx = fmaxf(mx, u);
    }
    if (lane == 31) wbuf[wid] = mx;
    __syncthreads();
    if (wid == 0) {
        float s = wbuf[lane];
        #pragma unroll
        for (int o = 1; o < 32; o <<= 1) {
            float u = __shfl_up_sync(0xffffffffu, s, o);
            if (lane >= o) s = fmaxf(s, u);
        }
        wbuf[lane] = s;
    }
    __syncthreads();
    float Mv = wid ? fmaxf(mx, wbuf[wid - 1]) : mx;
    g_m [base + t] = expf(m);
    g_Mx[base + t] = Mv;
    g_d0[base + t] = expf(-lfc - Mv);
}

// ---------------- mLSTM attention v9 (z now read from g_z) ----------------
#define KVSLOT 2816   // u32 per slab: 64 rows * 44 u32 (88 halves)
__global__ void __launch_bounds__(256, 2) attn_kernel(const float* __restrict__ normw,
                                                      const float* __restrict__ skipw) {
    extern __shared__ uint32_t smu[];
    uint32_t* Ks = smu;
    uint32_t* Vs = smu + 2 * KVSLOT;
    float* wms = (float*)(smu + 4 * KVSLOT);

    int bn = blockIdx.y;
    int b = bn >> 2, n = bn & 3;
    int tid = threadIdx.x, lane = tid & 31, warp = tid >> 5;
    int wm = warp & 3, wn = warp >> 2;
    int ln4 = lane >> 2, q4 = lane & 3;
    int r0 = wm * 16;
    int cb0 = wn * 32;
    int rr = r0 + ln4;
    const float scale = 0.11785113019775793f;
    const unsigned FULL = 0xffffffffu;

    uint32_t smbase = (uint32_t)__cvta_generic_to_shared(smu);

    int sOffG[5], sOffS[5];
    bool sIsV[5], sOK[5];
    #pragma unroll
    for (int u = 0; u < 5; u++) {
        int i = tid + u * 256;
        sOK[u]  = (i < 1152);
        sIsV[u] = (i >= 576);
        int j = sIsV[u] ? i - 576 : i;
        int r = j / 9, ch = j - r * 9;
        sOffG[u] = r * INNER + ch * 8;
        sOffS[u] = r * 44 + ch * 4;
    }

    int lm = lane >> 3, lr = lane & 7;

    #pragma unroll 1
    for (int sub = 0; sub < 2; sub++) {
        int R = sub == 0 ? (gridDim.x * 2 - 1 - blockIdx.x) : blockIdx.x;
        int S0 = R * 64;

        if (sub) __syncthreads();

        for (int i = tid; i < 2048; i += 256) {
            int slab = i >> 9, rem = i & 511;
            int r = rem >> 3, cc = 36 + (rem & 7);
            uint32_t val = (slab >= 2 && cc == 36) ? 0x00003C00u : 0u;
            smu[slab * KVSLOT + r * 44 + cc] = val;
        }
        float w0 = expf(-g_Mx[(size_t)bn * S_LEN + S0 + rr]) * scale;
        float w1 = expf(-g_Mx[(size_t)bn * S_LEN + S0 + rr + 8]) * scale;
        float d00 = g_d0[(size_t)bn * S_LEN + S0 + rr];
        float d01 = g_d0[(size_t)bn * S_LEN + S0 + rr + 8];
        if (tid < 64) wms[tid] = g_m[(size_t)bn * S_LEN + tid];

        const __half* kb = g_k + (size_t)(b * S_LEN) * INNER + n * 72;
        const __half* vb = g_v + (size_t)(b * S_LEN) * INNER + n * 72;

        #pragma unroll
        for (int u = 0; u < 5; u++) {
            if (!sOK[u]) continue;
            const __half* src = (sIsV[u] ? vb : kb) + sOffG[u];
            uint32_t* dst = (sIsV[u] ? Vs : Ks) + sOffS[u];
            cp_async16((uint32_t)__cvta_generic_to_shared(dst), src);
        }
        CP_COMMIT();

        uint32_t qf[5][4];
        {
            const __half* q0 = g_q + (size_t)(b * S_LEN + S0 + r0 + ln4) * INNER + n * 72;
            const __half* q1 = q0 + 8 * INNER;
            #pragma unroll
            for (int s = 0; s < 5; s++) {
                int c = s * 16 + 2 * q4;
                qf[s][0] = *(const uint32_t*)(q0 + c);
                qf[s][1] = *(const uint32_t*)(q1 + c);
                int c2 = c + 8;
                if (s < 4) {
                    qf[s][2] = *(const uint32_t*)(q0 + c2);
                    qf[s][3] = *(const uint32_t*)(q1 + c2);
                } else {
                    qf[s][2] = 0u; qf[s][3] = 0u;
                }
            }
        }
        __syncthreads();

        float o[10][4] = {};

        for (int ct = 0; ct <= R; ct++) {
            CP_WAIT0();
            __syncthreads();
            int cur = ct & 1, nxt = cur ^ 1;
            if (ct < R) {
                kb += 64 * INNER;
                vb += 64 * INNER;
                uint32_t* Kd = Ks + nxt * KVSLOT;
                uint32_t* Vd = Vs + nxt * KVSLOT;
                #pragma unroll
                for (int u = 0; u < 5; u++) {
                    if (!sOK[u]) continue;
                    const __half* src = (sIsV[u] ? vb : kb) + sOffG[u];
                    uint32_t* dst = (sIsV[u] ? Vd : Kd) + sOffS[u];
                    cp_async16((uint32_t)__cvta_generic_to_shared(dst), src);
                }
                CP_COMMIT();
                if (tid < 64) wms[nxt * 64 + tid] = g_m[(size_t)bn * S_LEN + (ct + 1) * 64 + tid];
            }
            uint32_t kbase = smbase + (cur * KVSLOT) * 4;
            uint32_t vbase = smbase + ((2 + cur) * KVSLOT) * 4;
            const float* wmc = wms + cur * 64;

            float pc[4][4] = {};
            #pragma unroll
            for (int s = 0; s < 5; s++) {
                #pragma unroll
                for (int p = 0; p < 2; p++) {
                    int nrow = cb0 + p * 16 + ((lm >> 1) << 3) + lr;
                    int kcol = s * 16 + ((lm & 1) << 3);
                    uint32_t addr = kbase + nrow * 176 + kcol * 2;
                    uint32_t kb0, kb1, kb2, kb3;
                    ldmx4(kb0, kb1, kb2, kb3, addr);
                    if (s < 4) {
                        mma_f16(pc[2 * p],     qf[s][0], qf[s][1], qf[s][2], qf[s][3], kb0, kb1);
                        mma_f16(pc[2 * p + 1], qf[s][0], qf[s][1], qf[s][2], qf[s][3], kb2, kb3);
                    } else {
                        mma_f16_k8(pc[2 * p],     qf[s][0], qf[s][1], kb0);
                        mma_f16_k8(pc[2 * p + 1], qf[s][0], qf[s][1], kb2);
                    }
                }
            }

            bool diag = (ct == R);
            uint32_t pa[2][4];
            #pragma unroll
            for (int p = 0; p < 2; p++) {
                #pragma unroll
                for (int hh = 0; hh < 2; hh++) {
                    int nf = 2 * p + hh;
                    int c0 = cb0 + nf * 8 + 2 * q4;
                    float wc0 = wmc[c0], wc1 = wmc[c0 + 1];
                    float v00 = pc[nf][0] * w0 * wc0;
                    float v01 = pc[nf][1] * w0 * wc1;
                    float v10 = pc[nf][2] * w1 * wc0;
                    float v11 = pc[nf][3] * w1 * wc1;
                    if (diag) {
                        if (c0 > rr)         v00 = 0.f;
                        if (c0 + 1 > rr)     v01 = 0.f;
                        if (c0 > rr + 8)     v10 = 0.f;
                        if (c0 + 1 > rr + 8) v11 = 0.f;
                    }
                    pa[p][hh * 2 + 0] = h2u(v00, v01);
                    pa[p][hh * 2 + 1] = h2u(v10, v11);
                }
            }

            #pragma unroll
            for (int p = 0; p < 2; p++) {
                int kb2 = cb0 + p * 16;
                #pragma unroll
                for (int pf = 0; pf < 5; pf++) {
                    int vrow = kb2 + ((lm & 1) << 3) + lr;
                    int vcol = pf * 16 + ((lm >> 1) << 3);
                    uint32_t addr = vbase + vrow * 176 + vcol * 2;
                    uint32_t vb0, vb1, vb2, vb3;
                    ldmx4t(vb0, vb1, vb2, vb3, addr);
                    mma_f16(o[2 * pf],     pa[p][0], pa[p][1], pa[p][2], pa[p][3], vb0, vb1);
                    mma_f16(o[2 * pf + 1], pa[p][0], pa[p][1], pa[p][2], pa[p][3], vb2, vb3);
                }
            }
        }

        __syncthreads();
        float* OsB = (float*)Ks;
        if (wn == 1) {
            #pragma unroll
            for (int nf = 0; nf < 9; nf++) {
                int c = nf * 8 + 2 * q4;
                OsB[rr * 76 + c]           = o[nf][0];
                OsB[rr * 76 + c + 1]       = o[nf][1];
                OsB[(rr + 8) * 76 + c]     = o[nf][2];
                OsB[(rr + 8) * 76 + c + 1] = o[nf][3];
            }
            if (q4 == 0) {
                OsB[rr * 76 + 72]       = o[9][0];
                OsB[(rr + 8) * 76 + 72] = o[9][2];
            }
        }
        __syncthreads();
        float* Of = (float*)Vs;
        if (wn == 0) {
            float p0 = __shfl_sync(FULL, o[9][0], lane & 28);
            float p1 = __shfl_sync(FULL, o[9][2], lane & 28);
            float rs0 = p0 + OsB[rr * 76 + 72];
            float rs1 = p1 + OsB[(rr + 8) * 76 + 72];
            float inv0 = 1.f / (fmaxf(fabsf(rs0), d00) + 1e-6f);
            float inv1 = 1.f / (fmaxf(fabsf(rs1), d01) + 1e-6f);
            #pragma unroll
            for (int nf = 0; nf < 9; nf++) {
                int c = nf * 8 + 2 * q4;
                Of[rr * 76 + c]           = (o[nf][0] + OsB[rr * 76 + c])           * inv0;
                Of[rr * 76 + c + 1]       = (o[nf][1] + OsB[rr * 76 + c + 1])       * inv0;
                Of[(rr + 8) * 76 + c]     = (o[nf][2] + OsB[(rr + 8) * 76 + c])     * inv1;
                Of[(rr + 8) * 76 + c + 1] = (o[nf][3] + OsB[(rr + 8) * 76 + c + 1]) * inv1;
            }
        }
        __syncthreads();

        float nw0 = normw[n * 72 + lane];
        float sk0 = skipw[n * 72 + lane];
        float nw1 = normw[n * 72 + 32 + lane];
        float sk1 = skipw[n * 72 + 32 + lane];
        float nw2 = 0.f, sk2 = 0.f;
        if (lane < 8) { nw2 = normw[n * 72 + 64 + lane]; sk2 = skipw[n * 72 + 64 + lane]; }

        #pragma unroll
        for (int r8 = 0; r8 < 8; r8++) {
            int r = warp * 8 + r8;
            float h0 = Of[r * 76 + lane];
            float h1 = Of[r * 76 + 32 + lane];
            float h2 = (lane < 8) ? Of[r * 76 + 64 + lane] : 0.f;
            float psum = h0 + h1 + h2;
            #pragma unroll
            for (int off = 16; off; off >>= 1) psum += __shfl_xor_sync(FULL, psum, off);
            float mean = psum * (1.f / 72.f);
            float dv0 = h0 - mean, dv1 = h1 - mean, dv2 = h2 - mean;
            float pss = dv0 * dv0 + dv1 * dv1 + ((lane < 8) ? dv2 * dv2 : 0.f);
            #pragma unroll
            for (int off = 16; off; off >>= 1) pss += __shfl_xor_sync(FULL, pss, off);
            float rstd = rsqrtf(pss * (1.f / 72.f) + 1e-5f);

            size_t row = (size_t)(b * S_LEN + S0 + r) * INNER;
            {
                int c = n * 72 + lane;
                float z = g_z[row + c];
                float val = dv0 * rstd * nw0 + sk0 * g_xa[row + c];
                g_hs[row + c] = __float2half_rn(val * (z / (1.f + expf(-z))));
            }
            {
                int c = n * 72 + 32 + lane;
                float z = g_z[row + c];
                float val = dv1 * rstd * nw1 + sk1 * g_xa[row + c];
                g_hs[row + c] = __float2half_rn(val * (z / (1.f + expf(-z))));
            }
            if (lane < 8) {
                int c = n * 72 + 64 + lane;
                float z = g_z[row + c];
                float val = dv2 * rstd * nw2 + sk2 * g_xa[row + c];
                g_hs[row + c] = __float2half_rn(val * (z / (1.f + expf(-z))));
            }
        }
    }
}

// ---------------- launch ----------------
extern "C" void kernel_launch(void* const* d_in, const int* in_sizes, int n_in,
                              void* d_out, int out_size) {
    const float* x           = (const float*)d_in[0];
    const float* proj_up_w   = (const float*)d_in[1];
    const float* q_w         = (const float*)d_in[2];
    const float* k_w         = (const float*)d_in[3];
    const float* v_w         = (const float*)d_in[4];
    const float* conv_w      = (const float*)d_in[5];
    const float* ig_w        = (const float*)d_in[6];
    const float* ig_b        = (const float*)d_in[7];
    const float* fg_w        = (const float*)d_in[8];
    const float* fg_b        = (const float*)d_in[9];
    const float* norm_w      = (const float*)d_in[10];
    const float* skip        = (const float*)d_in[11];
    const float* proj_down_w = (const float*)d_in[12];
    float* out = (float*)d_out;

    __half *phs, *pxh, *pwuph, *pwdnh;
    cudaGetSymbolAddress((void**)&phs,   g_hs);
    cudaGetSymbolAddress((void**)&pxh,   g_xh);
    cudaGetSymbolAddress((void**)&pwuph, g_wuph);
    cudaGetSymbolAddress((void**)&pwdnh, g_wdnh);

    // 0) fp32 -> fp16 converts (x, W_up, W_down)
    cvt_kernel<<<(XE + UE + DE) / 8 / 256, 256>>>(x, proj_up_w, proj_down_w);

    // 1) proj_up (pure fp16; epilogue splits x_m (fp16) | z (fp32))
    gemm_h16<128, 1><<<dim3(576 / 64, BS_TOT / 128), 256>>>(pxh, pwuph, nullptr, BS_TOT, 2 * INNER, DIMX);

    // 2) fused conv+silu+qkv+gates
    size_t smem_mid = (size_t)2 * 864 * 16;
    fused_mid_kernel<<<BS_TOT / 8, 256, smem_mid>>>(conv_w, q_w, k_w, v_w,
                                                    ig_w, ig_b, fg_w, fg_b);

    // 3) scan (stores exp(m))
    scan_kernel<<<32, S_LEN>>>();

    // 4) attention + LN + skip + silu(z): 8 balanced pairs x 32 bn
    size_t smem_attn = (size_t)(4 * KVSLOT + 128) * 4;
    cudaFuncSetAttribute(attn_kernel, cudaFuncAttributeMaxDynamicSharedMemorySize, (int)smem_attn);
    attn_kernel<<<dim3(8, 32), 256, smem_attn>>>(norm_w, skip);

    // 5) proj_down (pure fp16)
    gemm_h16<64, 0><<<dim3(DIMX / 64, BS_TOT / 64), 256>>>(phs, pwdnh, out, BS_TOT, DIMX, INNER);
}